// round 2
// baseline (speedup 1.0000x reference)
#include <cuda_runtime.h>
#include <math.h>
#include <stdint.h>

// ---------------------------------------------------------------------------
// Problem constants
// ---------------------------------------------------------------------------
namespace cfg {
constexpr int PRED = 100000, TOTAL = 120000, NUI = 200000, NODES = 220000;
constexpr float EPS = 1e-5f;

constexpr size_t S_NODE = (size_t)NODES * 64;
constexpr size_t S_NUI  = (size_t)NUI * 64;
constexpr size_t S_PRED = (size_t)PRED * 64;
constexpr size_t S_TOT  = (size_t)TOTAL * 64;

// float pool offsets
constexpr size_t O_E    = 0;                  // BN0 output (NODES x 64)
constexpr size_t O_UIE  = O_E + S_NODE;       // concat([pred_u, item_e]) (NUI x 64)
constexpr size_t O_FS   = O_UIE + S_NUI;
constexpr size_t O_FD   = O_FS + S_NUI;
constexpr size_t O_G0   = O_FD + S_NUI;       // u2i_emb (NUI x 64)
constexpr size_t O_G1   = O_G0 + S_NUI;       // iie (PRED x 64)
constexpr size_t O_I2U  = O_G1 + S_PRED;
constexpr size_t O_SOC  = O_I2U + S_PRED;
constexpr size_t O_SIE  = O_SOC + S_PRED;
constexpr size_t O_UIM  = O_SIE + S_PRED;     // user_item_embed
constexpr size_t O_TMP  = O_UIM + S_PRED;     // mlp pre-BN scratch
constexpr size_t O_HUP  = O_TMP + S_PRED;
constexpr size_t O_HUS  = O_HUP + S_PRED;
constexpr size_t O_SP   = O_HUS + S_PRED;     // h_m * softmax(...)
constexpr size_t O_USE  = O_SP + S_PRED;      // user_social_embed
constexpr size_t O_T1   = O_USE + S_PRED;     // cheb T1 (TOTAL x 64)
constexpr size_t O_T2   = O_T1 + S_TOT;
constexpr size_t O_H    = O_T2 + S_TOT;       // cheb1 out
constexpr size_t O_CH2  = O_H + S_TOT;        // cheb2 out
constexpr size_t O_DINV = O_CH2 + S_TOT;      // TOTAL
constexpr size_t O_STATS= O_DINV + TOTAL;     // 128 (sum, sumsq per col)
constexpr size_t FPOOL  = O_STATS + 128;

// int pool offsets
constexpr size_t I_CNT = 0;
constexpr size_t I_RP  = I_CNT + NUI + 2;
constexpr size_t I_BS  = I_RP + NUI + 2;
constexpr size_t I_BS2 = I_BS + 512;
constexpr size_t I_CSR = I_BS2 + 512;
constexpr size_t IPOOL = I_CSR + 1500000;
}  // namespace cfg

__device__ float g_f[cfg::FPOOL];
__device__ int   g_i[cfg::IPOOL];

// ---------------------------------------------------------------------------
// helpers
// ---------------------------------------------------------------------------
__device__ __forceinline__ float lrelu(float x, float s) { return x > 0.f ? x : s * x; }

// ---------------------------------------------------------------------------
// GEMM: Y[n x 64] = act( base + X[n x 64] @ W[64 x 64] )
// flags bit0: base = bias (else base = existing Y, accumulate)
// flags bit1: apply leaky_relu(0.01) at the end
// BM=64, BN=64, 128 threads, TM=8 x TN=4
// ---------------------------------------------------------------------------
__global__ __launch_bounds__(128) void gemm64(
    const float* __restrict__ X, const float* __restrict__ W,
    const float* __restrict__ bias, float* __restrict__ Y, int n, int flags)
{
    __shared__ float Xs[64 * 68];   // [k][r], stride 68 (16B-aligned rows, conflict-free)
    __shared__ float Ws[64 * 64];   // [k][c]
    const int t = threadIdx.x;
    const int m0 = blockIdx.x * 64;

    // load whole W (64x64) as float4
    {
        const float4* W4 = (const float4*)W;
        float4* Ws4 = (float4*)Ws;
#pragma unroll
        for (int i = 0; i < 8; i++) Ws4[i * 128 + t] = W4[i * 128 + t];
    }
    // load X tile transposed
#pragma unroll
    for (int i = 0; i < 8; i++) {
        int lin4 = i * 128 + t;            // 0..1023
        int r = lin4 >> 4, k4 = lin4 & 15;
        float4 v = make_float4(0.f, 0.f, 0.f, 0.f);
        if (m0 + r < n) v = *(const float4*)&X[(size_t)(m0 + r) * 64 + k4 * 4];
        Xs[(k4 * 4 + 0) * 68 + r] = v.x;
        Xs[(k4 * 4 + 1) * 68 + r] = v.y;
        Xs[(k4 * 4 + 2) * 68 + r] = v.z;
        Xs[(k4 * 4 + 3) * 68 + r] = v.w;
    }
    __syncthreads();

    const int tx = t & 15, ty = t >> 4;    // tx: 16 col groups of 4, ty: 8 row groups of 8
    float acc[8][4];
#pragma unroll
    for (int i = 0; i < 8; i++)
#pragma unroll
        for (int j = 0; j < 4; j++) acc[i][j] = 0.f;

#pragma unroll 8
    for (int k = 0; k < 64; k++) {
        float4 b  = *(const float4*)&Ws[k * 64 + tx * 4];
        float4 a0 = *(const float4*)&Xs[k * 68 + ty * 8];
        float4 a1 = *(const float4*)&Xs[k * 68 + ty * 8 + 4];
        float av[8] = {a0.x, a0.y, a0.z, a0.w, a1.x, a1.y, a1.z, a1.w};
        float bv[4] = {b.x, b.y, b.z, b.w};
#pragma unroll
        for (int i = 0; i < 8; i++)
#pragma unroll
            for (int j = 0; j < 4; j++) acc[i][j] += av[i] * bv[j];
    }

    const bool init = flags & 1, lk = flags & 2;
    float4 bb = make_float4(0.f, 0.f, 0.f, 0.f);
    if (init) bb = *(const float4*)&bias[tx * 4];
#pragma unroll
    for (int i = 0; i < 8; i++) {
        int row = m0 + ty * 8 + i;
        if (row >= n) break;
        float4 base = init ? bb : *(const float4*)&Y[(size_t)row * 64 + tx * 4];
        float4 o;
        o.x = base.x + acc[i][0];
        o.y = base.y + acc[i][1];
        o.z = base.z + acc[i][2];
        o.w = base.w + acc[i][3];
        if (lk) { o.x = lrelu(o.x, .01f); o.y = lrelu(o.y, .01f); o.z = lrelu(o.z, .01f); o.w = lrelu(o.w, .01f); }
        *(float4*)&Y[(size_t)row * 64 + tx * 4] = o;
    }
}

// ---------------------------------------------------------------------------
// BatchNorm
// ---------------------------------------------------------------------------
__global__ void bn_stats(const float* __restrict__ x, float* __restrict__ stats, int n)
{
    const int col = threadIdx.x & 63, rg = threadIdx.x >> 6;  // 256 threads
    float s = 0.f, q = 0.f;
    for (int r = blockIdx.x * 4 + rg; r < n; r += gridDim.x * 4) {
        float v = x[(size_t)r * 64 + col];
        s += v; q += v * v;
    }
    __shared__ float sh[2][4][64];
    sh[0][rg][col] = s; sh[1][rg][col] = q;
    __syncthreads();
    if (rg == 0) {
        s = sh[0][0][col] + sh[0][1][col] + sh[0][2][col] + sh[0][3][col];
        q = sh[1][0][col] + sh[1][1][col] + sh[1][2][col] + sh[1][3][col];
        atomicAdd(&stats[col], s);
        atomicAdd(&stats[64 + col], q);
    }
}

__global__ void bn_apply(const float* __restrict__ x, const float* __restrict__ stats,
                         const float* __restrict__ g, const float* __restrict__ b,
                         float* __restrict__ y, int n, int leaky)
{
    size_t idx = (size_t)blockIdx.x * blockDim.x + threadIdx.x;
    size_t tot = (size_t)n * 64;
    if (idx >= tot) return;
    int col = idx & 63;
    float mu  = stats[col] / (float)n;
    float var = stats[64 + col] / (float)n - mu * mu;
    float sc = rsqrtf(var + cfg::EPS) * g[col];
    float v = (x[idx] - mu) * sc + b[col];
    y[idx] = leaky ? lrelu(v, .01f) : v;
}

// ---------------------------------------------------------------------------
// CSR build
// ---------------------------------------------------------------------------
__global__ void edge_count(const int* __restrict__ dst, int m, int* __restrict__ cnt)
{
    int i = blockIdx.x * blockDim.x + threadIdx.x;
    if (i < m) atomicAdd(&cnt[dst[i]], 1);
}

__global__ void scan_block(const int* __restrict__ in, int* __restrict__ out,
                           int* __restrict__ bsums, int N)
{
    __shared__ int s[1024];
    int t = threadIdx.x, idx = blockIdx.x * 1024 + t;
    int v = idx < N ? in[idx] : 0;
    s[t] = v;
    __syncthreads();
    for (int off = 1; off < 1024; off <<= 1) {
        int a = (t >= off) ? s[t - off] : 0;
        __syncthreads();
        s[t] += a;
        __syncthreads();
    }
    if (idx < N) out[idx] = s[t] - v;          // exclusive
    if (t == 1023 && bsums) bsums[blockIdx.x] = s[1023];
}

__global__ void scan_add(int* __restrict__ rp, const int* __restrict__ bs2, int N)
{
    int idx = blockIdx.x * blockDim.x + threadIdx.x;
    if (idx < N) rp[idx] += bs2[idx >> 10];
}

__global__ void edge_scatter(const int* __restrict__ src, const int* __restrict__ dst, int m,
                             const int* __restrict__ rp, int* __restrict__ cnt,
                             int* __restrict__ csr)
{
    int i = blockIdx.x * blockDim.x + threadIdx.x;
    if (i >= m) return;
    int d = dst[i];
    int pos = rp[d] + atomicAdd(&cnt[d], 1);
    csr[pos] = src[i];
}

// ---------------------------------------------------------------------------
// GATv2 aggregation: warp per dst node, online softmax, all-register accum
// ---------------------------------------------------------------------------
__global__ void gat_agg(const int* __restrict__ rp, const int* __restrict__ cs,
                        const float* __restrict__ fs, const float* __restrict__ fd,
                        const float* __restrict__ attn, float* __restrict__ out, int n_out)
{
    int w = (blockIdx.x * blockDim.x + threadIdx.x) >> 5;
    if (w >= n_out) return;
    int lane = threadIdx.x & 31;
    float2 fdv = *(const float2*)&fd[(size_t)w * 64 + lane * 2];
    float2 at  = *(const float2*)&attn[lane * 2];
    float m = -INFINITY, den = 0.f;
    float2 acc = make_float2(0.f, 0.f);
    int beg = rp[w], end = rp[w + 1];
    for (int j = beg; j < end; ++j) {
        int s = __ldg(&cs[j]);
        float2 fv = *(const float2*)&fs[(size_t)s * 64 + lane * 2];
        float ex = lrelu(fv.x + fdv.x, .2f);
        float ey = lrelu(fv.y + fdv.y, .2f);
        float p = ex * at.x + ey * at.y;
#pragma unroll
        for (int o = 16; o; o >>= 1) p += __shfl_xor_sync(0xffffffffu, p, o);
        if (p <= m) {
            float wt = __expf(p - m);
            den += wt; acc.x += wt * fv.x; acc.y += wt * fv.y;
        } else {
            float r = __expf(m - p);   // first edge: exp(-inf)=0
            den = den * r + 1.f;
            acc.x = acc.x * r + fv.x;
            acc.y = acc.y * r + fv.y;
            m = p;
        }
    }
    float2 o;
    if (den > 0.f) { o.x = acc.x / den; o.y = acc.y / den; }
    else           { o.x = 0.f; o.y = 0.f; }
    o.x = lrelu(o.x, .01f); o.y = lrelu(o.y, .01f);
    *(float2*)&out[(size_t)w * 64 + lane * 2] = o;
}

// ---------------------------------------------------------------------------
// Cheb
// ---------------------------------------------------------------------------
__global__ void calc_dinv(const int* __restrict__ rp, float* __restrict__ dinv, int n)
{
    int i = blockIdx.x * blockDim.x + threadIdx.x;
    if (i >= n) return;
    int d = rp[i + 1] - rp[i];
    dinv[i] = rsqrtf((float)(d < 1 ? 1 : d));
}

// out = alpha * ( (2/lam)*(v - A_norm v) - v ) + beta * extra   (warp per node)
__global__ void cheb_lhat(const int* __restrict__ rp, const int* __restrict__ cs,
                          const float* __restrict__ dinv, const float* __restrict__ v,
                          const float* __restrict__ extra, const float* __restrict__ lamp,
                          float alpha, float beta, float* __restrict__ out, int n)
{
    int w = (blockIdx.x * blockDim.x + threadIdx.x) >> 5;
    if (w >= n) return;
    int lane = threadIdx.x & 31;
    float c = 2.f / lamp[0];
    float2 v2 = *(const float2*)&v[(size_t)w * 64 + lane * 2];
    float di = dinv[w];
    float2 acc = make_float2(0.f, 0.f);
    int beg = rp[w], end = rp[w + 1];
    for (int j = beg; j < end; ++j) {
        int s = __ldg(&cs[j]);
        float nm = di * dinv[s];
        float2 sv = *(const float2*)&v[(size_t)s * 64 + lane * 2];
        acc.x += nm * sv.x; acc.y += nm * sv.y;
    }
    float2 l;
    l.x = c * (v2.x - acc.x) - v2.x;
    l.y = c * (v2.y - acc.y) - v2.y;
    float2 r;
    if (extra) {
        float2 e2 = *(const float2*)&extra[(size_t)w * 64 + lane * 2];
        r.x = alpha * l.x + beta * e2.x;
        r.y = alpha * l.y + beta * e2.y;
    } else {
        r.x = alpha * l.x; r.y = alpha * l.y;
    }
    *(float2*)&out[(size_t)w * 64 + lane * 2] = r;
}

// ---------------------------------------------------------------------------
// misc elementwise
// ---------------------------------------------------------------------------
__global__ void build_uie(const float* __restrict__ e, float* __restrict__ uie)
{
    size_t idx = (size_t)blockIdx.x * blockDim.x + threadIdx.x;  // float4 index
    if (idx >= (size_t)cfg::NUI * 16) return;
    size_t row = idx >> 4;
    size_t srow = row < (size_t)cfg::PRED ? row : row + (size_t)(cfg::TOTAL - cfg::PRED);
    ((float4*)uie)[idx] = ((const float4*)e)[srow * 16 + (idx & 15)];
}

__global__ void soc_select(const float* __restrict__ i2u, const float* __restrict__ uie,
                           float* __restrict__ soc)
{
    int w = (blockIdx.x * blockDim.x + threadIdx.x) >> 5;
    if (w >= cfg::PRED) return;
    int lane = threadIdx.x & 31;
    float2 a = *(const float2*)&i2u[(size_t)w * 64 + lane * 2];
    float p = a.x + a.y;
#pragma unroll
    for (int o = 16; o; o >>= 1) p += __shfl_xor_sync(0xffffffffu, p, o);
    float2 o2 = (p != 0.f) ? a : *(const float2*)&uie[(size_t)w * 64 + lane * 2];
    *(float2*)&soc[(size_t)w * 64 + lane * 2] = o2;
}

// out = hA * hB * softmax(hA) rowwise
__global__ void hm_soft(const float* __restrict__ hA, const float* __restrict__ hB,
                        float* __restrict__ out)
{
    int w = (blockIdx.x * blockDim.x + threadIdx.x) >> 5;
    if (w >= cfg::PRED) return;
    int lane = threadIdx.x & 31;
    float2 a = *(const float2*)&hA[(size_t)w * 64 + lane * 2];
    float2 b = *(const float2*)&hB[(size_t)w * 64 + lane * 2];
    float mx = fmaxf(a.x, a.y);
#pragma unroll
    for (int o = 16; o; o >>= 1) mx = fmaxf(mx, __shfl_xor_sync(0xffffffffu, mx, o));
    float ex = __expf(a.x - mx), ey = __expf(a.y - mx);
    float s = ex + ey;
#pragma unroll
    for (int o = 16; o; o >>= 1) s += __shfl_xor_sync(0xffffffffu, s, o);
    float inv = 1.f / s;
    float2 o2;
    o2.x = a.x * b.x * ex * inv;
    o2.y = a.y * b.y * ey * inv;
    *(float2*)&out[(size_t)w * 64 + lane * 2] = o2;
}

// ---------------------------------------------------------------------------
// host orchestration
// ---------------------------------------------------------------------------
namespace {
inline int divup(int a, int b) { return (a + b - 1) / b; }

struct Ctx {
    float* f;  // g_f base
    int*   i;  // g_i base
};

void csr_build(const Ctx& c, const int* src, const int* dst, int m, int n)
{
    using namespace cfg;
    int* cnt = c.i + I_CNT;
    int* rp  = c.i + I_RP;
    int* bs  = c.i + I_BS;
    int* bs2 = c.i + I_BS2;
    int* csr = c.i + I_CSR;
    int N = n + 1;
    cudaMemsetAsync(cnt, 0, sizeof(int) * N);
    edge_count<<<divup(m, 256), 256>>>(dst, m, cnt);
    int nb = divup(N, 1024);
    scan_block<<<nb, 1024>>>(cnt, rp, bs, N);
    scan_block<<<1, 1024>>>(bs, bs2, nullptr, nb);
    scan_add<<<divup(N, 256), 256>>>(rp, bs2, N);
    cudaMemsetAsync(cnt, 0, sizeof(int) * N);
    edge_scatter<<<divup(m, 256), 256>>>(src, dst, m, rp, cnt, csr);
}

void run_bn(const Ctx& c, const float* x, const float* g, const float* b,
            float* y, int n, int leaky)
{
    using namespace cfg;
    float* stats = c.f + O_STATS;
    cudaMemsetAsync(stats, 0, 128 * sizeof(float));
    bn_stats<<<512, 256>>>(x, stats, n);
    size_t tot = (size_t)n * 64;
    bn_apply<<<(int)divup((int)tot, 256), 256>>>(x, stats, g, b, y, n, leaky);
}

void run_gemm(const float* X, const float* W, const float* bias, float* Y, int n, int flags)
{
    gemm64<<<divup(n, 64), 128>>>(X, W, bias, Y, n, flags);
}

// assumes CSR already built over this graph
void run_gat(const Ctx& c, int li, const float* x, int n, int n_out,
             const float* Wl, const float* bl, const float* Wr, const float* br,
             const float* attn, float* out)
{
    using namespace cfg;
    float* fs = c.f + O_FS;
    float* fd = c.f + O_FD;
    run_gemm(x, Wl + (size_t)li * 4096, bl + (size_t)li * 64, fs, n, 1);
    run_gemm(x, Wr + (size_t)li * 4096, br + (size_t)li * 64, fd, n_out, 1);
    gat_agg<<<divup(n_out * 32, 256), 256>>>(c.i + I_RP, c.i + I_CSR, fs, fd,
                                             attn + (size_t)li * 64, out, n_out);
}

void run_mlp(const Ctx& c, int li, const float* A, const float* B,
             const float* Wm, const float* bm, const float* gm, const float* betam,
             float* out)
{
    using namespace cfg;
    float* tmp = c.f + O_TMP;
    run_gemm(A, Wm + (size_t)li * 8192,        bm + (size_t)li * 64, tmp, PRED, 1);
    run_gemm(B, Wm + (size_t)li * 8192 + 4096, nullptr,              tmp, PRED, 0);
    run_bn(c, tmp, gm + (size_t)li * 64, betam + (size_t)li * 64, out, PRED, 1);
}

void run_cheb(const Ctx& c, const float* x, const float* chebW, const float* chebB,
              const float* lamp, float* out)
{
    using namespace cfg;
    float* t1 = c.f + O_T1;
    float* t2 = c.f + O_T2;
    const float* dinv = c.f + O_DINV;
    const int* rp = c.i + I_RP;
    const int* cs = c.i + I_CSR;
    int g = divup(TOTAL * 32, 256);
    cheb_lhat<<<g, 256>>>(rp, cs, dinv, x, nullptr, lamp, 1.f, 0.f, t1, TOTAL);
    cheb_lhat<<<g, 256>>>(rp, cs, dinv, t1, x, lamp, 2.f, -1.f, t2, TOTAL);
    run_gemm(x,  chebW,        chebB,   out, TOTAL, 1);
    run_gemm(t1, chebW + 4096, nullptr, out, TOTAL, 0);
    run_gemm(t2, chebW + 8192, nullptr, out, TOTAL, 2);  // acc + leaky
}
}  // namespace

extern "C" void kernel_launch(void* const* d_in, const int* in_sizes, int n_in,
                              void* d_out, int out_size)
{
    using namespace cfg;
    Ctx c;
    cudaGetSymbolAddress((void**)&c.f, g_f);
    cudaGetSymbolAddress((void**)&c.i, g_i);

    const float* emb    = (const float*)d_in[0];
    const float* bn0_g  = (const float*)d_in[1];
    const float* bn0_b  = (const float*)d_in[2];
    const float* gat_Wl = (const float*)d_in[3];
    const float* gat_bl = (const float*)d_in[4];
    const float* gat_Wr = (const float*)d_in[5];
    const float* gat_br = (const float*)d_in[6];
    const float* gat_at = (const float*)d_in[7];
    const float* cheb_W = (const float*)d_in[8];
    const float* cheb_b = (const float*)d_in[9];
    const float* mlp_W  = (const float*)d_in[10];
    const float* mlp_b  = (const float*)d_in[11];
    const float* mlp_g  = (const float*)d_in[12];
    const float* mlp_be = (const float*)d_in[13];
    const float* lamp   = (const float*)d_in[14];
    const int* u2i_src = (const int*)d_in[15]; const int* u2i_dst = (const int*)d_in[16];
    const int* rc_src  = (const int*)d_in[17]; const int* rc_dst  = (const int*)d_in[18];
    const int* i2u_src = (const int*)d_in[19]; const int* i2u_dst = (const int*)d_in[20];
    const int* sn_src  = (const int*)d_in[22]; const int* sn_dst  = (const int*)d_in[23];
    const int* snn_src = (const int*)d_in[24]; const int* snn_dst = (const int*)d_in[25];
    const int m_u2i = in_sizes[15], m_rc = in_sizes[17], m_i2u = in_sizes[19];
    const int m_sn = in_sizes[22], m_snn = in_sizes[24];

    float* E   = c.f + O_E;
    float* UIE = c.f + O_UIE;
    float* G0  = c.f + O_G0;
    float* G1  = c.f + O_G1;
    float* I2U = c.f + O_I2U;
    float* SOC = c.f + O_SOC;
    float* SIE = c.f + O_SIE;
    float* UIM = c.f + O_UIM;
    float* HUP = c.f + O_HUP;
    float* HUS = c.f + O_HUS;
    float* SP  = c.f + O_SP;
    float* USE = c.f + O_USE;
    float* H   = c.f + O_H;
    float* CH2 = c.f + O_CH2;
    float* out = (float*)d_out;

    // ---- BN0 over full emb ----
    run_bn(c, emb, bn0_g, bn0_b, E, NODES, 0);

    // ---- uie = concat([e[:PRED], e[-ITEM:]]) ----
    build_uie<<<divup(NUI * 16, 256), 256>>>(E, UIE);

    // ---- GAT0: u2i over uie (all NUI rows needed) ----
    csr_build(c, u2i_src, u2i_dst, m_u2i, NUI);
    run_gat(c, 0, UIE, NUI, NUI, gat_Wl, gat_bl, gat_Wr, gat_br, gat_at, G0);

    // ---- GAT1: rc over u2i_emb, only [:PRED] consumed ----
    csr_build(c, rc_src, rc_dst, m_rc, NUI);
    run_gat(c, 1, G0, NUI, PRED, gat_Wl, gat_bl, gat_Wr, gat_br, gat_at, G1);

    // ---- GAT2: i2u over su = uie[:PRED] ----
    csr_build(c, i2u_src, i2u_dst, m_i2u, PRED);
    run_gat(c, 2, UIE, PRED, PRED, gat_Wl, gat_bl, gat_Wr, gat_br, gat_at, I2U);

    // ---- soc = where(rowsum(i2u_emb)!=0, i2u_emb, uie[:PRED]) ----
    soc_select<<<divup(PRED * 32, 256), 256>>>(I2U, UIE, SOC);

    // ---- GAT3: sn over soc ----
    csr_build(c, sn_src, sn_dst, m_sn, PRED);
    run_gat(c, 3, SOC, PRED, PRED, gat_Wl, gat_bl, gat_Wr, gat_br, gat_at, SIE);

    // ---- mlp0: user_item_embed = mlp(concat([iie, sie])) ----
    run_mlp(c, 0, G1, SIE, mlp_W, mlp_b, mlp_g, mlp_be, UIM);

    // ---- snn graph: cheb x2 + GAT4 ----
    csr_build(c, snn_src, snn_dst, m_snn, TOTAL);
    calc_dinv<<<divup(TOTAL, 256), 256>>>(c.i + I_RP, c.f + O_DINV, TOTAL);
    run_cheb(c, E, cheb_W, cheb_b, lamp, H);     // T0 = total_u = E[:TOTAL]
    run_cheb(c, H, cheb_W, cheb_b, lamp, CH2);
    run_gat(c, 4, CH2, TOTAL, PRED, gat_Wl, gat_bl, gat_Wr, gat_br, gat_at, USE);

    // ---- mlp1 / mlp2 ----
    run_mlp(c, 1, UIM, E, mlp_W, mlp_b, mlp_g, mlp_be, HUP);   // pred_u = E[:PRED]
    run_mlp(c, 2, USE, E, mlp_W, mlp_b, mlp_g, mlp_be, HUS);

    // ---- h_new_P = mlp3(concat([h_m*softmax(h_uP), h_uP])) ----
    hm_soft<<<divup(PRED * 32, 256), 256>>>(HUP, HUS, SP);
    run_mlp(c, 3, SP, HUP, mlp_W, mlp_b, mlp_g, mlp_be, out);

    // ---- h_new_S = mlp4(concat([h_m*softmax(h_uS), h_uS])) ----
    hm_soft<<<divup(PRED * 32, 256), 256>>>(HUS, HUP, SP);
    run_mlp(c, 4, SP, HUS, mlp_W, mlp_b, mlp_g, mlp_be, out + S_PRED);
}